// round 7
// baseline (speedup 1.0000x reference)
#include <cuda_runtime.h>
#include <cuda_bf16.h>

// Identity copy (1x1 avgpool, stride 1): 51,380,224 fp32 = 205.5 MB each way.
//
// R5 (deeper MLP) and R6 (256-bit accesses) were both neutral -> demand side
// saturated at ~7.25 TB/s combined. Remaining structural lever: the R3 config
// ran ~7 waves of blocks (6272 blocks / 888 concurrent); each wave boundary
// drains/refills in-flight memory demand. This round: persistent grid-stride
// kernel at exactly one wave (888 blocks = 148 SMs x 6 resident), so every SM
// streams continuously with zero block launch/retire churn.
//
// Body identical to the best-measured R3 kernel: float4, UNROLL=8,
// streaming hints both sides (working set 2x205MB >> 126MB L2).

#define THREADS 256
#define UNROLL  8                       // float4s per thread per tile
#define TILE    (THREADS * UNROLL)      // 2048 float4s = 64 KB per tile
#define BLOCKS  888                     // 148 SMs * 6 resident blocks = 1 wave

__global__ __launch_bounds__(THREADS) void copy_kernel(
    const float4* __restrict__ src, float4* __restrict__ dst, int ntiles)
{
    // ntiles = 6272 tiles of 2048 float4s; each block strides through
    // ~7 tiles. Exact cover, no tail predicates inside a tile.
    for (int tile = blockIdx.x; tile < ntiles; tile += BLOCKS) {
        int base = tile * TILE + threadIdx.x;
        float4 v[UNROLL];
        #pragma unroll
        for (int u = 0; u < UNROLL; u++)
            v[u] = __ldcs(&src[base + u * THREADS]);
        #pragma unroll
        for (int u = 0; u < UNROLL; u++)
            __stcs(&dst[base + u * THREADS], v[u]);
    }
}

extern "C" void kernel_launch(void* const* d_in, const int* in_sizes, int n_in,
                              void* d_out, int out_size) {
    const float4* x = (const float4*)d_in[0];
    float4* out = (float4*)d_out;
    // out_size = 51,380,224 floats = 12,845,056 float4s = 6272 tiles of 2048.
    int ntiles = (out_size / 4) / TILE;  // 6272
    copy_kernel<<<BLOCKS, THREADS>>>(x, out, ntiles);
}

// round 8
// speedup vs baseline: 1.0393x; 1.0393x over previous
#include <cuda_runtime.h>
#include <cuda_bf16.h>

// Identity copy (1x1 avgpool, stride 1): 51,380,224 fp32 = 205.5 MB each way.
//
// R7 persistent grid REGRESSED (loop back-edge serializes tile loads behind
// prior stores -> demand sag). Reverting to the R3 launch shape (6272
// independent blocks, all 8 loads front-batched).
//
// This round's single change: ASYMMETRIC cache policy.
//   loads  : __ldcs  (streaming — don't pollute L2 with the read stream)
//   stores : default write-back (let the 126MB L2 buffer dirty lines and
//            drain them to DRAM in long sequential bursts -> fewer
//            read<->write bus turnarounds, the last credible source of the
//            ~21% idle DRAM cycles)

#define THREADS 256
#define UNROLL  8   // float4s per thread

__global__ __launch_bounds__(THREADS) void copy_kernel(
    const float4* __restrict__ src, float4* __restrict__ dst)
{
    // Each block owns THREADS*UNROLL = 2048 consecutive float4s (64 KB).
    // Grid covers the array exactly: 6272 blocks * 2048 = 12,845,056.
    int base = blockIdx.x * (THREADS * UNROLL) + threadIdx.x;

    float4 v[UNROLL];
    #pragma unroll
    for (int u = 0; u < UNROLL; u++)
        v[u] = __ldcs(&src[base + u * THREADS]);
    #pragma unroll
    for (int u = 0; u < UNROLL; u++)
        dst[base + u * THREADS] = v[u];   // default .wb store
}

extern "C" void kernel_launch(void* const* d_in, const int* in_sizes, int n_in,
                              void* d_out, int out_size) {
    const float4* x = (const float4*)d_in[0];
    float4* out = (float4*)d_out;
    // out_size = 51,380,224 floats = 12,845,056 float4s
    // = 6272 blocks * (256 threads * 8 float4s). Exact cover, no tail.
    int n4 = out_size / 4;
    int per_block = THREADS * UNROLL;
    int blocks = n4 / per_block;  // 6272
    copy_kernel<<<blocks, THREADS>>>(x, out);
}

// round 9
// speedup vs baseline: 1.0528x; 1.0129x over previous
#include <cuda_runtime.h>
#include <cuda_bf16.h>

// FINAL — MyAvgPool2D_56444460204139 on GB300 (sm_103a).
//
// The reference with H=W=56, OUT=56 reduces to a 1x1/stride-1 avgpool ==
// identity. The task is an out-of-place copy of 51,380,224 fp32
// (205.5 MB read + 205.5 MB write).
//
// Converged configuration (kernel 56.5-56.6us = 7.27 TB/s combined, ~91% of
// the 8 TB/s HBM3e spec; residual is intrinsic read<->write bus turnaround):
//  - float4 (LDG.E.128/STG.E.128), UNROLL=8 front-batched loads
//    (MLP depth saturated here: 16 was neutral, 256-bit accesses neutral)
//  - streaming cache hints both sides (working set 2x205MB >> 126MB L2;
//    .wb stores measured neutral)
//  - exact non-persistent grid, no tail predicates (6272 blocks x 2048
//    float4s; persistent single-wave variant measured SLOWER — loop
//    back-edge serializes next-tile loads behind prior stores)

#define THREADS 256
#define UNROLL  8   // float4s per thread

__global__ __launch_bounds__(THREADS) void copy_kernel(
    const float4* __restrict__ src, float4* __restrict__ dst)
{
    // Each block owns THREADS*UNROLL = 2048 consecutive float4s (64 KB),
    // per-thread accesses strided by THREADS for full coalescing.
    int base = blockIdx.x * (THREADS * UNROLL) + threadIdx.x;

    float4 v[UNROLL];
    #pragma unroll
    for (int u = 0; u < UNROLL; u++)
        v[u] = __ldcs(&src[base + u * THREADS]);
    #pragma unroll
    for (int u = 0; u < UNROLL; u++)
        __stcs(&dst[base + u * THREADS], v[u]);
}

extern "C" void kernel_launch(void* const* d_in, const int* in_sizes, int n_in,
                              void* d_out, int out_size) {
    const float4* x = (const float4*)d_in[0];
    float4* out = (float4*)d_out;
    // out_size = 51,380,224 floats = 12,845,056 float4s
    // = 6272 blocks * (256 threads * 8 float4s). Exact cover, no tail.
    int n4 = out_size / 4;
    int per_block = THREADS * UNROLL;
    int blocks = n4 / per_block;  // 6272
    copy_kernel<<<blocks, THREADS>>>(x, out);
}

// round 10
// speedup vs baseline: 1.0559x; 1.0030x over previous
#include <cuda_runtime.h>
#include <cuda_bf16.h>

// MyAvgPool2D_56444460204139 on GB300 (sm_103a): 1x1/stride-1 avgpool ==
// identity -> out-of-place copy of 51,380,224 fp32 (205.5 MB each way).
//
// Converged at kernel ~56.6us = 7.27 TB/s combined (~91% of 8 TB/s HBM3e);
// residual is intrinsic read<->write bus turnaround. Probed & settled:
//   MLP depth (8 saturates), 256-bit accesses (neutral), persistent grid
//   (regressed), store cache policy (neutral).
// Final tie-break probe: block geometry 256 -> 512 threads (same UNROLL=8,
// 3136 blocks x 128KB contiguous). Changes CTA->SM placement interleave /
// per-SM L2-die affinity; expected neutral +-1%, kept only if it wins.

#define THREADS 512
#define UNROLL  8   // float4s per thread

__global__ __launch_bounds__(THREADS) void copy_kernel(
    const float4* __restrict__ src, float4* __restrict__ dst)
{
    // Each block owns THREADS*UNROLL = 4096 consecutive float4s (128 KB),
    // per-thread accesses strided by THREADS for full coalescing.
    int base = blockIdx.x * (THREADS * UNROLL) + threadIdx.x;

    float4 v[UNROLL];
    #pragma unroll
    for (int u = 0; u < UNROLL; u++)
        v[u] = __ldcs(&src[base + u * THREADS]);
    #pragma unroll
    for (int u = 0; u < UNROLL; u++)
        __stcs(&dst[base + u * THREADS], v[u]);
}

extern "C" void kernel_launch(void* const* d_in, const int* in_sizes, int n_in,
                              void* d_out, int out_size) {
    const float4* x = (const float4*)d_in[0];
    float4* out = (float4*)d_out;
    // out_size = 51,380,224 floats = 12,845,056 float4s
    // = 3136 blocks * (512 threads * 8 float4s). Exact cover, no tail.
    int n4 = out_size / 4;
    int per_block = THREADS * UNROLL;
    int blocks = n4 / per_block;  // 3136
    copy_kernel<<<blocks, THREADS>>>(x, out);
}